// round 1
// baseline (speedup 1.0000x reference)
#include <cuda_runtime.h>

#define NEXP 2048
#define NDICT 65536
#define NPIX 1600
#define KTOP 10
#define BM 128
#define BN 128
#define BK 16

// Scratch (device globals: allocation-free per harness rules)
__device__ float g_cos[(size_t)NEXP * NDICT];   // 512 MB cos-sim matrix
__device__ float g_mq[NEXP];
__device__ float g_iq[NEXP];
__device__ float g_md[NDICT];
__device__ float g_id[NDICT];

// ---------------------------------------------------------------------------
// Per-row mean and inverse centered-norm:  inv = rsqrt(sum(x^2) - mean*sum(x))
// which == 1/||x - mean(x)||.  which=0 -> experimental (g_mq/g_iq),
// which=1 -> dictionary (g_md/g_id).
// ---------------------------------------------------------------------------
__global__ void rowstats_kernel(const float* __restrict__ X, int which) {
    int row = blockIdx.x;
    const float* x = X + (size_t)row * NPIX;
    float s = 0.f, s2 = 0.f;
    for (int i = threadIdx.x; i < NPIX; i += blockDim.x) {
        float v = x[i];
        s += v;
        s2 += v * v;
    }
#pragma unroll
    for (int o = 16; o > 0; o >>= 1) {
        s  += __shfl_down_sync(0xffffffffu, s, o);
        s2 += __shfl_down_sync(0xffffffffu, s2, o);
    }
    __shared__ float sh_s[8], sh_s2[8];
    int w = threadIdx.x >> 5, l = threadIdx.x & 31;
    if (l == 0) { sh_s[w] = s; sh_s2[w] = s2; }
    __syncthreads();
    if (threadIdx.x == 0) {
        float ts = 0.f, ts2 = 0.f;
#pragma unroll
        for (int i = 0; i < 8; i++) { ts += sh_s[i]; ts2 += sh_s2[i]; }
        float m = ts / (float)NPIX;
        float inv = rsqrtf(ts2 - m * ts);
        if (which == 0) { g_mq[row] = m; g_iq[row] = inv; }
        else            { g_md[row] = m; g_id[row] = inv; }
    }
}

// ---------------------------------------------------------------------------
// C[m][n] = dot(A[m,:], B[n,:]) with fused centering/normalization epilogue:
//   cos = (dot - NPIX*mq*md) * iq * id   -> g_cos
// 128x128x16 tiles, 256 threads, 8x8 per thread, double-buffered smem,
// smem stored transposed [BK][BM] for conflict-free float4 fragment reads.
// ---------------------------------------------------------------------------
__global__ void __launch_bounds__(256, 2)
gemm_kernel(const float* __restrict__ A, const float* __restrict__ B) {
    __shared__ float As[2][BK][BM];
    __shared__ float Bs[2][BK][BN];

    const int tid = threadIdx.x;
    const int m_base = blockIdx.y * BM;
    const int n_base = blockIdx.x * BN;

    // Loader mapping: 2048 floats per tile per matrix = 256 threads * 2 float4.
    const int ak  = (tid & 3) << 2;   // k offset within BK: 0,4,8,12
    const int ar0 = tid >> 2;         // rows 0..63
    const int ar1 = ar0 + 64;         // rows 64..127

    const float* Ag0 = A + (size_t)(m_base + ar0) * NPIX + ak;
    const float* Ag1 = A + (size_t)(m_base + ar1) * NPIX + ak;
    const float* Bg0 = B + (size_t)(n_base + ar0) * NPIX + ak;
    const float* Bg1 = B + (size_t)(n_base + ar1) * NPIX + ak;

    // Prologue: tile 0 -> smem[0]
    {
        float4 a0 = *(const float4*)(Ag0);
        float4 a1 = *(const float4*)(Ag1);
        float4 b0 = *(const float4*)(Bg0);
        float4 b1 = *(const float4*)(Bg1);
        As[0][ak + 0][ar0] = a0.x; As[0][ak + 1][ar0] = a0.y;
        As[0][ak + 2][ar0] = a0.z; As[0][ak + 3][ar0] = a0.w;
        As[0][ak + 0][ar1] = a1.x; As[0][ak + 1][ar1] = a1.y;
        As[0][ak + 2][ar1] = a1.z; As[0][ak + 3][ar1] = a1.w;
        Bs[0][ak + 0][ar0] = b0.x; Bs[0][ak + 1][ar0] = b0.y;
        Bs[0][ak + 2][ar0] = b0.z; Bs[0][ak + 3][ar0] = b0.w;
        Bs[0][ak + 0][ar1] = b1.x; Bs[0][ak + 1][ar1] = b1.y;
        Bs[0][ak + 2][ar1] = b1.z; Bs[0][ak + 3][ar1] = b1.w;
    }
    __syncthreads();

    const int m0 = (tid >> 4) << 3;   // 0..120
    const int n0 = (tid & 15) << 3;   // 0..120

    float acc[8][8];
#pragma unroll
    for (int i = 0; i < 8; i++)
#pragma unroll
        for (int j = 0; j < 8; j++) acc[i][j] = 0.f;

    const int NT = NPIX / BK;  // 100
    int buf = 0;
    for (int t = 0; t < NT; t++) {
        float4 na0, na1, nb0, nb1;
        const bool has_next = (t + 1 < NT);
        if (has_next) {
            int off = (t + 1) * BK;
            na0 = *(const float4*)(Ag0 + off);
            na1 = *(const float4*)(Ag1 + off);
            nb0 = *(const float4*)(Bg0 + off);
            nb1 = *(const float4*)(Bg1 + off);
        }
#pragma unroll
        for (int kk = 0; kk < BK; kk++) {
            float4 av0 = *(const float4*)&As[buf][kk][m0];
            float4 av1 = *(const float4*)&As[buf][kk][m0 + 4];
            float4 bv0 = *(const float4*)&Bs[buf][kk][n0];
            float4 bv1 = *(const float4*)&Bs[buf][kk][n0 + 4];
            float am[8] = {av0.x, av0.y, av0.z, av0.w, av1.x, av1.y, av1.z, av1.w};
            float bn[8] = {bv0.x, bv0.y, bv0.z, bv0.w, bv1.x, bv1.y, bv1.z, bv1.w};
#pragma unroll
            for (int i = 0; i < 8; i++)
#pragma unroll
                for (int j = 0; j < 8; j++)
                    acc[i][j] = fmaf(am[i], bn[j], acc[i][j]);
        }
        if (has_next) {
            int nb = buf ^ 1;
            As[nb][ak + 0][ar0] = na0.x; As[nb][ak + 1][ar0] = na0.y;
            As[nb][ak + 2][ar0] = na0.z; As[nb][ak + 3][ar0] = na0.w;
            As[nb][ak + 0][ar1] = na1.x; As[nb][ak + 1][ar1] = na1.y;
            As[nb][ak + 2][ar1] = na1.z; As[nb][ak + 3][ar1] = na1.w;
            Bs[nb][ak + 0][ar0] = nb0.x; Bs[nb][ak + 1][ar0] = nb0.y;
            Bs[nb][ak + 2][ar0] = nb0.z; Bs[nb][ak + 3][ar0] = nb0.w;
            Bs[nb][ak + 0][ar1] = nb1.x; Bs[nb][ak + 1][ar1] = nb1.y;
            Bs[nb][ak + 2][ar1] = nb1.z; Bs[nb][ak + 3][ar1] = nb1.w;
            buf = nb;
        }
        __syncthreads();
    }

    // Epilogue: apply centering correction + normalization, write cos matrix.
    float mqv[8], iqv[8], mdv[8], idv[8];
#pragma unroll
    for (int i = 0; i < 8; i++) {
        mqv[i] = g_mq[m_base + m0 + i];
        iqv[i] = g_iq[m_base + m0 + i];
        mdv[i] = g_md[n_base + n0 + i];
        idv[i] = g_id[n_base + n0 + i];
    }
#pragma unroll
    for (int i = 0; i < 8; i++) {
        float* dst = &g_cos[(size_t)(m_base + m0 + i) * NDICT + (n_base + n0)];
        float corr = (float)NPIX * mqv[i];
        float4 o0, o1;
        o0.x = (acc[i][0] - corr * mdv[0]) * iqv[i] * idv[0];
        o0.y = (acc[i][1] - corr * mdv[1]) * iqv[i] * idv[1];
        o0.z = (acc[i][2] - corr * mdv[2]) * iqv[i] * idv[2];
        o0.w = (acc[i][3] - corr * mdv[3]) * iqv[i] * idv[3];
        o1.x = (acc[i][4] - corr * mdv[4]) * iqv[i] * idv[4];
        o1.y = (acc[i][5] - corr * mdv[5]) * iqv[i] * idv[5];
        o1.z = (acc[i][6] - corr * mdv[6]) * iqv[i] * idv[6];
        o1.w = (acc[i][7] - corr * mdv[7]) * iqv[i] * idv[7];
        *(float4*)dst = o0;
        *(float4*)(dst + 4) = o1;
    }
}

// ---------------------------------------------------------------------------
// Per-row top-10 over 65536 cos values. One block per experimental row.
// Per-thread branchless sorted insertion into 10 registers, then smem dump
// (2560 candidates) and 10 rounds of block-wide argmax with JAX tie-breaking
// (higher value wins; on exact tie, smaller dictionary index wins).
// Output layout (float32): [ang 2048*10][idx 2048*10][orient 2048*10*4]
// ---------------------------------------------------------------------------
__global__ void topk_kernel(const float* __restrict__ so3, float* __restrict__ out) {
    const int row = blockIdx.x;
    const int tid = threadIdx.x;
    const float* c = g_cos + (size_t)row * NDICT;

    float tv[KTOP];
    int   ti[KTOP];
#pragma unroll
    for (int i = 0; i < KTOP; i++) { tv[i] = -3.0f; ti[i] = 0x7fffffff; }

    for (int i = tid; i < NDICT; i += blockDim.x) {
        float v = c[i];
        if (v > tv[KTOP - 1]) {
            // shift entries smaller than v down by one (reads originals: p desc)
#pragma unroll
            for (int p = KTOP - 1; p >= 1; p--) {
                bool mv = (tv[p - 1] < v);
                if (mv) { tv[p] = tv[p - 1]; ti[p] = ti[p - 1]; }
            }
            // insert at first slot whose value < v
            bool placed = false;
#pragma unroll
            for (int p = 0; p < KTOP; p++) {
                if (!placed && tv[p] < v) { tv[p] = v; ti[p] = i; placed = true; }
            }
        }
    }

    __shared__ float sval[256 * KTOP];
    __shared__ int   sidx[256 * KTOP];
    __shared__ float rv[256];
    __shared__ int   ri[256];
#pragma unroll
    for (int j = 0; j < KTOP; j++) {
        sval[tid * KTOP + j] = tv[j];
        sidx[tid * KTOP + j] = ti[j];
    }
    __syncthreads();

    for (int r = 0; r < KTOP; r++) {
        // local argmax over this thread's 10 candidates
        float bv = -4.0f; int bi = 0x7fffffff;
        for (int j = 0; j < KTOP; j++) {
            float v = sval[tid * KTOP + j];
            int   x = sidx[tid * KTOP + j];
            if (v > bv || (v == bv && x < bi)) { bv = v; bi = x; }
        }
        rv[tid] = bv; ri[tid] = bi;
        __syncthreads();
        for (int s = 128; s > 0; s >>= 1) {
            if (tid < s) {
                float v2 = rv[tid + s]; int i2 = ri[tid + s];
                if (v2 > rv[tid] || (v2 == rv[tid] && i2 < ri[tid])) {
                    rv[tid] = v2; ri[tid] = i2;
                }
            }
            __syncthreads();
        }
        float wv = rv[0];
        int   wi = ri[0];
        // consume winner
        for (int j = 0; j < KTOP; j++)
            if (sidx[tid * KTOP + j] == wi) sval[tid * KTOP + j] = -4.0f;
        if (tid == 0) {
            float cc = fminf(fmaxf(wv, -1.0f), 1.0f);
            out[(size_t)row * KTOP + r] = acosf(cc);
            out[(size_t)NEXP * KTOP + (size_t)row * KTOP + r] = (float)wi;
            const float* q = so3 + (size_t)wi * 4;
            float* od = out + 2 * (size_t)NEXP * KTOP + ((size_t)row * KTOP + r) * 4;
            od[0] = q[0]; od[1] = q[1]; od[2] = q[2]; od[3] = q[3];
        }
        __syncthreads();
    }
}

extern "C" void kernel_launch(void* const* d_in, const int* in_sizes, int n_in,
                              void* d_out, int out_size) {
    const float* Q   = (const float*)d_in[0];  // experimental_data [2048,1600]
    const float* P   = (const float*)d_in[1];  // patterns          [65536,1600]
    const float* SO3 = (const float*)d_in[2];  // so3_samples_fz    [65536,4]
    float* out = (float*)d_out;

    rowstats_kernel<<<NEXP, 256>>>(Q, 0);
    rowstats_kernel<<<NDICT, 256>>>(P, 1);

    dim3 grid(NDICT / BN, NEXP / BM);  // (512, 16)
    gemm_kernel<<<grid, 256>>>(Q, P);

    topk_kernel<<<NEXP, 256>>>(SO3, out);
}